// round 15
// baseline (speedup 1.0000x reference)
#include <cuda_runtime.h>
#include <cuda_fp16.h>
#include <cstdint>

// Problem constants
#define D_   256
#define H_   256
#define G3   768          // 3*H (gate dim, fp32 path)
#define G2   512          // packed GEMM K: [hi(256) | lo(256)] fp16
#define B_   8
#define TT   512          // T
#define TD   511          // decode steps (T-1)
#define V_   32000
#define MROWS 4096        // padded M rows = B * 512
#define NRW   4088        // real (t,b) rows = 511*8

// ---------------- device scratch (module-static, allowed) ----------------
__device__ __align__(16) float   g_WihT[D_ * G3];             // [k][j] transposed W_ih
__device__ __align__(16) float   g_WhhT[H_ * G3];             // [k][j] transposed W_hh
__device__ __align__(16) float   g_GX[(size_t)NRW * G3];      // gx per (t*8+b) row
__device__ __align__(16) float   g_Hstate[B_ * H_];           // h carried between chunks
__device__ __align__(16) __half  g_Apack[(size_t)MROWS * G2]; // [h_hi | h_lo] fp16
__device__ __align__(16) __half  g_Bpack[(size_t)V_ * 256];   // w_hi fp16 (single copy)

// ---------------- prep: transposes + zero pad rows ----------------
__global__ void k_prep_w(const float* __restrict__ W_ih, const float* __restrict__ W_hh) {
    int idx = blockIdx.x * blockDim.x + threadIdx.x;
    const int NW = G3 * D_;   // 196608
    if (idx < NW) {
        int j = idx / D_, k = idx % D_;
        g_WihT[k * G3 + j] = W_ih[idx];
    } else if (idx < 2 * NW) {
        int i2 = idx - NW;
        int j = i2 / H_, k = i2 % H_;
        g_WhhT[k * G3 + j] = W_hh[i2];
    } else if (idx < 2 * NW + B_ * G2) {
        int i2 = idx - 2 * NW;
        int b = i2 / G2, c = i2 % G2;
        g_Apack[((size_t)(b * TT + TD)) * G2 + c] = __float2half(0.f);
    }
}

// ---------------- prep: build fp16 B operand (single w_hi copy) ----------------
__global__ void k_bpack(const float* __restrict__ W_out) {
    int n = blockIdx.x;
    int k = threadIdx.x;
    g_Bpack[(size_t)n * 256 + k] = __float2half(W_out[(size_t)n * H_ + k]);
}

// ---------------- GX: gx[t,b,:] = W_ih @ emb[tok] + b_ih ----------------
__global__ void __launch_bounds__(256) k_gx(const int* __restrict__ seqs,
                                            const float* __restrict__ emb,
                                            const float* __restrict__ b_ih) {
    __shared__ float Xs[16][256];
    const int r0  = blockIdx.x * 16;
    const int tid = threadIdx.x;

    for (int j = 0; j < 16; j++) {
        int rp = r0 + j;
        float v = 0.f;
        if (rp < NRW) {
            int t = rp >> 3, b = rp & 7;
            int tok = (t == 0) ? 0 : seqs[b * TT + (t - 1)];
            tok = min(max(tok, 0), V_ - 1);
            v = emb[(size_t)tok * D_ + tid];
        }
        Xs[j][tid] = v;
    }
    __syncthreads();

    float aR[16], aZ[16], aN[16];
#pragma unroll
    for (int j = 0; j < 16; j++) { aR[j] = 0.f; aZ[j] = 0.f; aN[j] = 0.f; }

#pragma unroll 4
    for (int k = 0; k < 256; k++) {
        float wr = g_WihT[k * G3 + tid];
        float wz = g_WihT[k * G3 + 256 + tid];
        float wn = g_WihT[k * G3 + 512 + tid];
#pragma unroll
        for (int j = 0; j < 16; j++) {
            float x = Xs[j][k];
            aR[j] = fmaf(wr, x, aR[j]);
            aZ[j] = fmaf(wz, x, aZ[j]);
            aN[j] = fmaf(wn, x, aN[j]);
        }
    }

    float br = b_ih[tid], bz = b_ih[256 + tid], bn = b_ih[512 + tid];
    for (int j = 0; j < 16; j++) {
        int rp = r0 + j;
        if (rp < NRW) {
            size_t base = (size_t)rp * G3;
            g_GX[base + tid]        = aR[j] + br;
            g_GX[base + 256 + tid]  = aZ[j] + bz;
            g_GX[base + 512 + tid]  = aN[j] + bn;
        }
    }
}

// ---------------- Recurrence chunk: 8 clusters x 8 CTAs, steps [t0,t1) ----------
__device__ __forceinline__ void cluster_sync_() {
    asm volatile("barrier.cluster.arrive.aligned;" ::: "memory");
    asm volatile("barrier.cluster.wait.aligned;" ::: "memory");
}
__device__ __forceinline__ void mbar_init(uint32_t a, uint32_t cnt) {
    asm volatile("mbarrier.init.shared.b64 [%0], %1;" :: "r"(a), "r"(cnt) : "memory");
}
__device__ __forceinline__ void mbar_expect_tx(uint32_t a, uint32_t bytes) {
    asm volatile("mbarrier.arrive.expect_tx.shared.b64 _, [%0], %1;" :: "r"(a), "r"(bytes) : "memory");
}
__device__ __forceinline__ void mbar_wait(uint32_t a, uint32_t par) {
    asm volatile(
        "{\n\t.reg .pred P;\n"
        "WL%=:\n\t"
        "mbarrier.try_wait.parity.acquire.cluster.shared::cta.b64 P, [%0], %1;\n\t"
        "@!P bra WL%=;\n\t}"
        :: "r"(a), "r"(par) : "memory");
}
// remote store + tx-credit on dest CTA's mbarrier (data and mbar in SAME dest CTA)
__device__ __forceinline__ void st_async_b32(uint32_t daddr, uint32_t mbar, int rank, float v) {
    uint32_t ra, rm;
    asm volatile("mapa.shared::cluster.u32 %0, %1, %2;" : "=r"(ra) : "r"(daddr), "r"(rank));
    asm volatile("mapa.shared::cluster.u32 %0, %1, %2;" : "=r"(rm) : "r"(mbar), "r"(rank));
    asm volatile("st.async.shared::cluster.mbarrier::complete_tx::bytes.b32 [%0], %1, [%2];"
                 :: "r"(ra), "r"(__float_as_uint(v)), "r"(rm) : "memory");
}
__device__ __forceinline__ float sigmoid_f(float x) {
    return __fdividef(1.f, 1.f + __expf(-x));
}
__device__ __forceinline__ float tanh_f(float x) {
    return 1.f - __fdividef(2.f, 1.f + __expf(2.f * x));
}

__global__ void __launch_bounds__(256, 1) __cluster_dims__(8, 1, 1)
k_recur(const float* __restrict__ b_hh, int t0, int t1) {
    const int b     = blockIdx.x >> 3;    // batch lane (cluster id)
    const int crank = blockIdx.x & 7;     // CTA rank in cluster
    const int tid   = threadIdx.x;        // 0..255
    const int khg   = tid >> 5;           // k-group 0..7 (32 k each)
    const int jq    = tid & 31;           // h-lane within CTA's owned 32

    __shared__ float  h_sm[2][256];       // double-buffered by step parity
    __shared__ float3 part[8][32];        // per-kgroup (ghr,ghz,ghn) partials
    __shared__ __align__(8) unsigned long long mb_h_s;

    const uint32_t hsm_a = (uint32_t)__cvta_generic_to_shared(h_sm);
    const uint32_t mb_h  = (uint32_t)__cvta_generic_to_shared(&mb_h_s);

    // init: h(t0) from carried state (zeroed for t0==0 by host-ordered prep)
    h_sm[0][tid] = (t0 == 0) ? 0.f : g_Hstate[b * H_ + tid];
    if (tid == 0) mbar_init(mb_h, 1);

    float hreg = 0.f, bhr = 0.f, bhz = 0.f, bhn = 0.f;
    const int hidx = crank * 32 + tid;    // owned h index (tid<32)
    if (tid < 32) {
        hreg = (t0 == 0) ? 0.f : g_Hstate[b * H_ + hidx];
        bhr = b_hh[hidx];
        bhz = b_hh[256 + hidx];
        bhn = b_hh[512 + hidx];
    }

    // register-resident W slice: 32 k x 3 gate-columns for h-index (crank*32 + jq)
    float wrR[32], wrZ[32], wrN[32];
    {
        const int col = crank * 32 + jq;
        const float* wp = g_WhhT + (size_t)(khg * 32) * G3 + col;
#pragma unroll
        for (int kk = 0; kk < 32; kk++) {
            wrR[kk] = wp[(size_t)kk * G3];
            wrZ[kk] = wp[(size_t)kk * G3 + 256];
            wrN[kk] = wp[(size_t)kk * G3 + 512];
        }
    }
    __syncthreads();
    cluster_sync_();   // mbarrier + h(t0) visible cluster-wide before any st.async

    // gx pipeline: preload first step
    float gxr = 0.f, gxz = 0.f, gxn = 0.f;
    if (tid < 32) {
        const float* gp = g_GX + (size_t)(t0 * 8 + b) * G3 + hidx;
        gxr = __ldg(gp);
        gxz = __ldg(gp + 256);
        gxn = __ldg(gp + 512);
    }

    for (int t = t0; t < t1; t++) {
        const uint32_t par = (t - t0) & 1;
        if (tid == 0) mbar_expect_tx(mb_h, 256 * 4);

        // prefetch gx for NEXT step (covered by this step's FMA + wait)
        float ngr = 0.f, ngz = 0.f, ngn = 0.f;
        if (tid < 32) {
            int tn = (t + 1 < t1) ? t + 1 : t;
            const float* gp = g_GX + (size_t)(tn * 8 + b) * G3 + hidx;
            ngr = __ldg(gp);
            ngz = __ldg(gp + 256);
            ngn = __ldg(gp + 512);
        }

        // ---- FMA phase on h(t) in buffer par ----
        float aR = 0.f, aZ = 0.f, aN = 0.f;
        const float* hb = h_sm[par] + khg * 32;
#pragma unroll
        for (int kk = 0; kk < 32; kk++) {
            float hk = hb[kk];
            aR = fmaf(wrR[kk], hk, aR);
            aZ = fmaf(wrZ[kk], hk, aZ);
            aN = fmaf(wrN[kk], hk, aN);
        }
        part[khg][jq] = make_float3(aR, aZ, aN);
        __syncthreads();

        // ---- owner threads: reduce 8 k-groups + gate combine, all local ----
        if (tid < 32) {
            float ghr = bhr, ghz = bhz, ghn = bhn;
#pragma unroll
            for (int g = 0; g < 8; g++) {
                float3 p = part[g][tid];
                ghr += p.x; ghz += p.y; ghn += p.z;
            }
            float r  = sigmoid_f(gxr + ghr);
            float z  = sigmoid_f(gxz + ghz);
            float n  = tanh_f(gxn + r * ghn);
            float hn = (1.f - z) * n + z * hreg;
            hreg = hn;

            // broadcast h(t+1) into buffer par^1 of every CTA (tx-counted)
            uint32_t ha = hsm_a + ((par ^ 1) * 256 + hidx) * 4;
#pragma unroll
            for (int c = 0; c < 8; c++) st_async_b32(ha, mb_h, c, hn);

            // emit fp16 split A row: [hi | lo]
            __half hi = __float2half(hn);
            __half lo = __float2half(hn - __half2float(hi));
            size_t m = (size_t)(b * TT + t) * G2;
            g_Apack[m + hidx]       = hi;
            g_Apack[m + 256 + hidx] = lo;
        }
        gxr = ngr; gxz = ngz; gxn = ngn;

        // all threads: h(t+1) fully landed in buffer par^1
        mbar_wait(mb_h, par);
    }

    // persist h for next chunk
    if (tid < 32) g_Hstate[b * H_ + hidx] = hreg;

    cluster_sync_();   // no CTA exits while peers may still target its smem
}

// ---------------- Logits GEMM quarter: tiles with t in [128*tq, 128*tq+128) ----
#define BM 128
#define BN 128
#define BK 64
#define KSTAGES 8    // 512/64
#define STG_SZ 32768 // 16KB A + 16KB B per stage
#define SMEM_GEMM (3 * STG_SZ)

__device__ __forceinline__ void cp16(uint32_t dst, const void* src) {
    asm volatile("cp.async.cg.shared.global [%0], [%1], 16;" :: "r"(dst), "l"(src));
}
__device__ __forceinline__ void ldsm4(uint32_t* r, uint32_t addr) {
    asm volatile("ldmatrix.sync.aligned.m8n8.x4.shared.b16 {%0,%1,%2,%3}, [%4];"
                 : "=r"(r[0]), "=r"(r[1]), "=r"(r[2]), "=r"(r[3]) : "r"(addr));
}
__device__ __forceinline__ void mma_f16(float* c, const uint32_t* a, uint32_t b0, uint32_t b1) {
    asm volatile(
        "mma.sync.aligned.m16n8k16.row.col.f32.f16.f16.f32 "
        "{%0,%1,%2,%3}, {%4,%5,%6,%7}, {%8,%9}, {%0,%1,%2,%3};"
        : "+f"(c[0]), "+f"(c[1]), "+f"(c[2]), "+f"(c[3])
        : "r"(a[0]), "r"(a[1]), "r"(a[2]), "r"(a[3]), "r"(b0), "r"(b1));
}

__global__ void __launch_bounds__(256) k_gemm(const float* __restrict__ b_out,
                                              float* __restrict__ out, int tq) {
    extern __shared__ __half smem[];
    const int bM = blockIdx.y * 512 + tq * BM;   // one tile per b per quarter
    const int bN = blockIdx.x * BN;
    const int tid  = threadIdx.x;
    const int warp = tid >> 5;
    const int lane = tid & 31;
    const int wm = warp >> 2;        // 0..1
    const int wn = warp & 3;         // 0..3

    uint32_t s_base = (uint32_t)__cvta_generic_to_shared(smem);

    float acc[4][4][4];
#pragma unroll
    for (int i = 0; i < 4; i++)
#pragma unroll
        for (int j = 0; j < 4; j++)
#pragma unroll
            for (int c = 0; c < 4; c++) acc[i][j][c] = 0.f;

    const int lr = tid >> 3;   // 0..31
    const int lc = tid & 7;    // 16B chunk

    auto load_stage = [&](int s) {
        int buf = s % 3;
        uint32_t sA = s_base + buf * STG_SZ;
        uint32_t sB = sA + 16384;
        // A: K-col = s*64 (hi then lo); B: K-col = (s&3)*64 (w_hi reused)
        const __half* gA = g_Apack + (size_t)(bM + lr) * G2 + s * BK + lc * 8;
        const __half* gB = g_Bpack + (size_t)(bN + lr) * 256 + (s & 3) * BK + lc * 8;
#pragma unroll
        for (int i = 0; i < 4; i++) {
            int row = lr + i * 32;
            uint32_t dA = sA + row * 128 + ((lc ^ (row & 7)) << 4);
            cp16(dA, gA + (size_t)i * 32 * G2);
        }
#pragma unroll
        for (int i = 0; i < 4; i++) {
            int row = lr + i * 32;
            uint32_t dB = sB + row * 128 + ((lc ^ (row & 7)) << 4);
            cp16(dB, gB + (size_t)i * 32 * 256);
        }
        asm volatile("cp.async.commit_group;");
    };

    load_stage(0);
    load_stage(1);

    for (int s = 0; s < KSTAGES; s++) {
        if (s + 2 < KSTAGES) {
            load_stage(s + 2);
            asm volatile("cp.async.wait_group 2;");
        } else if (s + 1 < KSTAGES) {
            asm volatile("cp.async.wait_group 1;");
        } else {
            asm volatile("cp.async.wait_group 0;");
        }
        __syncthreads();

        int buf = s % 3;
        uint32_t baseA = s_base + buf * STG_SZ;
        uint32_t baseB = baseA + 16384;
        const int rin = lane & 15;
        const int hib = lane >> 4;

#pragma unroll
        for (int kk = 0; kk < 4; kk++) {
            uint32_t afr[4][4];
#pragma unroll
            for (int mt = 0; mt < 4; mt++) {
                int row = wm * 64 + mt * 16 + rin;
                int c16 = kk * 2 + hib;
                uint32_t addr = baseA + row * 128 + ((c16 ^ (row & 7)) << 4);
                ldsm4(afr[mt], addr);
            }
            uint32_t bfr[2][4];
#pragma unroll
            for (int np = 0; np < 2; np++) {
                int row = wn * 32 + np * 16 + rin;
                int c16 = kk * 2 + hib;
                uint32_t addr = baseB + row * 128 + ((c16 ^ (row & 7)) << 4);
                ldsm4(bfr[np], addr);
            }
#pragma unroll
            for (int mt = 0; mt < 4; mt++)
#pragma unroll
                for (int nt = 0; nt < 4; nt++) {
                    int np = nt >> 1, wv = nt & 1;
                    mma_f16(acc[mt][nt], afr[mt], bfr[np][wv], bfr[np][wv + 2]);
                }
        }
        __syncthreads();
    }

    // epilogue: + b_out, scatter to [b, t, v] skipping padded t=511 rows
    const int tig = lane & 3;
    const int gid = lane >> 2;
#pragma unroll
    for (int nt = 0; nt < 4; nt++) {
        int col = bN + wn * 32 + nt * 8 + tig * 2;
        float2 bo = *reinterpret_cast<const float2*>(b_out + col);
#pragma unroll
        for (int mt = 0; mt < 4; mt++) {
            int row0 = bM + wm * 64 + mt * 16 + gid;
#pragma unroll
            for (int h = 0; h < 2; h++) {
                int rr = row0 + h * 8;
                int t = rr & 511, bb = rr >> 9;
                if (t < TD) {
                    float2 v;
                    v.x = acc[mt][nt][2 * h + 0] + bo.x;
                    v.y = acc[mt][nt][2 * h + 1] + bo.y;
                    *reinterpret_cast<float2*>(out + ((size_t)(bb * TD + t)) * V_ + col) = v;
                }
            }
        }
    }
}

// ---------------- launch: forked-stream pipeline ----------------
extern "C" void kernel_launch(void* const* d_in, const int* in_sizes, int n_in,
                              void* d_out, int out_size) {
    (void)in_sizes; (void)n_in; (void)out_size;
    const int*   seqs  = (const int*)d_in[1];
    const float* emb   = (const float*)d_in[2];
    const float* W_ih  = (const float*)d_in[3];
    const float* W_hh  = (const float*)d_in[4];
    const float* b_ih  = (const float*)d_in[5];
    const float* b_hh  = (const float*)d_in[6];
    const float* W_out = (const float*)d_in[7];
    const float* b_out = (const float*)d_in[8];
    float* out = (float*)d_out;

    static cudaStream_t s2 = nullptr;
    static cudaEvent_t evr[4], evj;
    if (!s2) {
        cudaStreamCreateWithFlags(&s2, cudaStreamNonBlocking);
        for (int i = 0; i < 4; i++) cudaEventCreateWithFlags(&evr[i], cudaEventDisableTiming);
        cudaEventCreateWithFlags(&evj, cudaEventDisableTiming);
    }

    static cudaFuncAttributes fa_done = {};
    cudaFuncSetAttribute(k_gemm, cudaFuncAttributeMaxDynamicSharedMemorySize, SMEM_GEMM);
    (void)fa_done;

    k_prep_w<<<(2 * G3 * D_ + B_ * G2 + 255) / 256, 256>>>(W_ih, W_hh);
    k_bpack<<<V_, 256>>>(W_out);
    k_gx<<<256, 256>>>(seqs, emb, b_ih);

    const int tcut[5] = {0, 128, 256, 384, TD};
    dim3 ggrid(V_ / BN, B_);

    for (int q = 0; q < 4; q++) {
        k_recur<<<64, 256>>>(b_hh, tcut[q], tcut[q + 1]);
        if (q < 3) {
            // fork: GEMM quarter q runs on s2 concurrently with recur chunk q+1
            cudaEventRecord(evr[q], 0);
            cudaStreamWaitEvent(s2, evr[q], 0);
            k_gemm<<<ggrid, 256, SMEM_GEMM, s2>>>(b_out, out, q);
        }
    }
    // final quarter on the main stream (after recur chunk 3)
    k_gemm<<<ggrid, 256, SMEM_GEMM>>>(b_out, out, 3);

    // join side stream back before capture ends
    cudaEventRecord(evj, s2);
    cudaStreamWaitEvent(0, evj, 0);
}

// round 17
// speedup vs baseline: 1.3148x; 1.3148x over previous
#include <cuda_runtime.h>
#include <cuda_fp16.h>
#include <cstdint>

// Problem constants
#define D_   256
#define H_   256
#define G3   768          // 3*H (gate dim, fp32 path)
#define G2   512          // packed GEMM K: [hi(256) | lo(256)] fp16
#define B_   8
#define TT   512          // T
#define TD   511          // decode steps (T-1)
#define V_   32000
#define MROWS 4096        // padded M rows = B * 512
#define NRW   4088        // real (t,b) rows = 511*8
#define NTILE_Q 2000      // 250 N-tiles x 8 batch per quarter

// ---------------- device scratch (module-static, allowed) ----------------
__device__ __align__(16) float   g_WihT[D_ * G3];             // [k][j] transposed W_ih
__device__ __align__(16) float   g_WhhT[H_ * G3];             // [k][j] transposed W_hh
__device__ __align__(16) float   g_GX[(size_t)NRW * G3];      // gx per (t*8+b) row
__device__ __align__(16) __half  g_Apack[(size_t)MROWS * G2]; // [h_hi | h_lo] fp16
__device__ __align__(16) __half  g_Bpack[(size_t)V_ * 256];   // w_hi fp16 (single copy)
__device__ int g_ctr[4];                                      // per-quarter tile counters
__device__ int g_prog;                                        // recur progress: 64 per quarter

// ---------------- prep: transposes + zero pad rows ----------------
__global__ void k_prep_w(const float* __restrict__ W_ih, const float* __restrict__ W_hh) {
    int idx = blockIdx.x * blockDim.x + threadIdx.x;
    const int NW = G3 * D_;   // 196608
    if (idx < NW) {
        int j = idx / D_, k = idx % D_;
        g_WihT[k * G3 + j] = W_ih[idx];
    } else if (idx < 2 * NW) {
        int i2 = idx - NW;
        int j = i2 / H_, k = i2 % H_;
        g_WhhT[k * G3 + j] = W_hh[i2];
    } else if (idx < 2 * NW + B_ * G2) {
        int i2 = idx - 2 * NW;
        int b = i2 / G2, c = i2 % G2;
        g_Apack[((size_t)(b * TT + TD)) * G2 + c] = __float2half(0.f);
    }
}

// ---------------- prep: build fp16 B operand (single w_hi copy) ----------------
__global__ void k_bpack(const float* __restrict__ W_out) {
    int n = blockIdx.x;
    int k = threadIdx.x;
    g_Bpack[(size_t)n * 256 + k] = __float2half(W_out[(size_t)n * H_ + k]);
}

// ---------------- GX: gx[t,b,:] = W_ih @ emb[tok] + b_ih (also resets counters) ----
__global__ void __launch_bounds__(256) k_gx(const int* __restrict__ seqs,
                                            const float* __restrict__ emb,
                                            const float* __restrict__ b_ih) {
    if (blockIdx.x == 0 && threadIdx.x < 5) {
        if (threadIdx.x < 4) g_ctr[threadIdx.x] = 0;
        else                 g_prog = 0;
    }
    __shared__ float Xs[16][256];
    const int r0  = blockIdx.x * 16;
    const int tid = threadIdx.x;

    for (int j = 0; j < 16; j++) {
        int rp = r0 + j;
        float v = 0.f;
        if (rp < NRW) {
            int t = rp >> 3, b = rp & 7;
            int tok = (t == 0) ? 0 : seqs[b * TT + (t - 1)];
            tok = min(max(tok, 0), V_ - 1);
            v = emb[(size_t)tok * D_ + tid];
        }
        Xs[j][tid] = v;
    }
    __syncthreads();

    float aR[16], aZ[16], aN[16];
#pragma unroll
    for (int j = 0; j < 16; j++) { aR[j] = 0.f; aZ[j] = 0.f; aN[j] = 0.f; }

#pragma unroll 4
    for (int k = 0; k < 256; k++) {
        float wr = g_WihT[k * G3 + tid];
        float wz = g_WihT[k * G3 + 256 + tid];
        float wn = g_WihT[k * G3 + 512 + tid];
#pragma unroll
        for (int j = 0; j < 16; j++) {
            float x = Xs[j][k];
            aR[j] = fmaf(wr, x, aR[j]);
            aZ[j] = fmaf(wz, x, aZ[j]);
            aN[j] = fmaf(wn, x, aN[j]);
        }
    }

    float br = b_ih[tid], bz = b_ih[256 + tid], bn = b_ih[512 + tid];
    for (int j = 0; j < 16; j++) {
        int rp = r0 + j;
        if (rp < NRW) {
            size_t base = (size_t)rp * G3;
            g_GX[base + tid]        = aR[j] + br;
            g_GX[base + 256 + tid]  = aZ[j] + bz;
            g_GX[base + 512 + tid]  = aN[j] + bn;
        }
    }
}

// ---------------- Recurrence: single launch, 8 clusters x 8 CTAs ----------
__device__ __forceinline__ void cluster_sync_() {
    asm volatile("barrier.cluster.arrive.aligned;" ::: "memory");
    asm volatile("barrier.cluster.wait.aligned;" ::: "memory");
}
__device__ __forceinline__ void mbar_init(uint32_t a, uint32_t cnt) {
    asm volatile("mbarrier.init.shared.b64 [%0], %1;" :: "r"(a), "r"(cnt) : "memory");
}
__device__ __forceinline__ void mbar_expect_tx(uint32_t a, uint32_t bytes) {
    asm volatile("mbarrier.arrive.expect_tx.shared.b64 _, [%0], %1;" :: "r"(a), "r"(bytes) : "memory");
}
__device__ __forceinline__ void mbar_wait(uint32_t a, uint32_t par) {
    asm volatile(
        "{\n\t.reg .pred P;\n"
        "WL%=:\n\t"
        "mbarrier.try_wait.parity.acquire.cluster.shared::cta.b64 P, [%0], %1;\n\t"
        "@!P bra WL%=;\n\t}"
        :: "r"(a), "r"(par) : "memory");
}
__device__ __forceinline__ void st_async_b32(uint32_t daddr, uint32_t mbar, int rank, float v) {
    uint32_t ra, rm;
    asm volatile("mapa.shared::cluster.u32 %0, %1, %2;" : "=r"(ra) : "r"(daddr), "r"(rank));
    asm volatile("mapa.shared::cluster.u32 %0, %1, %2;" : "=r"(rm) : "r"(mbar), "r"(rank));
    asm volatile("st.async.shared::cluster.mbarrier::complete_tx::bytes.b32 [%0], %1, [%2];"
                 :: "r"(ra), "r"(__float_as_uint(v)), "r"(rm) : "memory");
}
__device__ __forceinline__ float sigmoid_f(float x) {
    return __fdividef(1.f, 1.f + __expf(-x));
}
__device__ __forceinline__ float tanh_f(float x) {
    return 1.f - __fdividef(2.f, 1.f + __expf(2.f * x));
}

// Dynamic smem is intentionally oversized (unused) so no GEMM CTA (96KB) can ever
// co-reside on a recur SM: 140KB + 96KB > 228KB.
#define RECUR_DSMEM 135168

__global__ void __launch_bounds__(256, 1) __cluster_dims__(8, 1, 1)
k_recur(const float* __restrict__ b_hh) {
    extern __shared__ float dyn_unused[];
    (void)dyn_unused;
    const int b     = blockIdx.x >> 3;    // batch lane (cluster id)
    const int crank = blockIdx.x & 7;     // CTA rank in cluster
    const int tid   = threadIdx.x;        // 0..255
    const int khg   = tid >> 5;           // k-group 0..7 (32 k each)
    const int jq    = tid & 31;           // h-lane within CTA's owned 32

    __shared__ float  h_sm[2][256];       // double-buffered by step parity
    __shared__ float3 part[8][32];        // per-kgroup (ghr,ghz,ghn) partials
    __shared__ __align__(8) unsigned long long mb_h_s;

    const uint32_t hsm_a = (uint32_t)__cvta_generic_to_shared(h_sm);
    const uint32_t mb_h  = (uint32_t)__cvta_generic_to_shared(&mb_h_s);

    h_sm[0][tid] = 0.f;
    if (tid == 0) mbar_init(mb_h, 1);

    float hreg = 0.f, bhr = 0.f, bhz = 0.f, bhn = 0.f;
    const int hidx = crank * 32 + tid;    // owned h index (tid<32)
    if (tid < 32) {
        bhr = b_hh[hidx];
        bhz = b_hh[256 + hidx];
        bhn = b_hh[512 + hidx];
    }

    // register-resident W slice: 32 k x 3 gate-columns for h-index (crank*32 + jq)
    float wrR[32], wrZ[32], wrN[32];
    {
        const int col = crank * 32 + jq;
        const float* wp = g_WhhT + (size_t)(khg * 32) * G3 + col;
#pragma unroll
        for (int kk = 0; kk < 32; kk++) {
            wrR[kk] = wp[(size_t)kk * G3];
            wrZ[kk] = wp[(size_t)kk * G3 + 256];
            wrN[kk] = wp[(size_t)kk * G3 + 512];
        }
    }
    __syncthreads();
    cluster_sync_();

    // gx pipeline: preload step 0
    float gxr = 0.f, gxz = 0.f, gxn = 0.f;
    if (tid < 32) {
        const float* gp = g_GX + (size_t)b * G3 + hidx;
        gxr = __ldg(gp);
        gxz = __ldg(gp + 256);
        gxn = __ldg(gp + 512);
    }

    for (int t = 0; t < TD; t++) {
        const uint32_t par = t & 1;
        if (tid == 0) mbar_expect_tx(mb_h, 256 * 4);

        float ngr = 0.f, ngz = 0.f, ngn = 0.f;
        if (tid < 32) {
            int tn = (t + 1 < TD) ? t + 1 : t;
            const float* gp = g_GX + (size_t)(tn * 8 + b) * G3 + hidx;
            ngr = __ldg(gp);
            ngz = __ldg(gp + 256);
            ngn = __ldg(gp + 512);
        }

        // ---- FMA phase on h(t) ----
        float aR = 0.f, aZ = 0.f, aN = 0.f;
        const float* hb = h_sm[par] + khg * 32;
#pragma unroll
        for (int kk = 0; kk < 32; kk++) {
            float hk = hb[kk];
            aR = fmaf(wrR[kk], hk, aR);
            aZ = fmaf(wrZ[kk], hk, aZ);
            aN = fmaf(wrN[kk], hk, aN);
        }
        part[khg][jq] = make_float3(aR, aZ, aN);
        __syncthreads();

        if (tid < 32) {
            float ghr = bhr, ghz = bhz, ghn = bhn;
#pragma unroll
            for (int g = 0; g < 8; g++) {
                float3 p = part[g][tid];
                ghr += p.x; ghz += p.y; ghn += p.z;
            }
            float r  = sigmoid_f(gxr + ghr);
            float z  = sigmoid_f(gxz + ghz);
            float n  = tanh_f(gxn + r * ghn);
            float hn = (1.f - z) * n + z * hreg;
            hreg = hn;

            uint32_t ha = hsm_a + ((par ^ 1) * 256 + hidx) * 4;
#pragma unroll
            for (int c = 0; c < 8; c++) st_async_b32(ha, mb_h, c, hn);

            __half hi = __float2half(hn);
            __half lo = __float2half(hn - __half2float(hi));
            size_t m = (size_t)(b * TT + t) * G2;
            g_Apack[m + hidx]       = hi;
            g_Apack[m + 256 + hidx] = lo;
        }
        gxr = ngr; gxz = ngz; gxn = ngn;

        mbar_wait(mb_h, par);

        // quarter-complete signal (t = 127/255/383; quarter 3 needs no signal)
        if ((t & 127) == 127 && t < 384) {
            if (tid < 32) __threadfence();
            __syncthreads();
            if (tid == 0) atomicAdd(&g_prog, 1);
        }
    }

    cluster_sync_();
}

// ---------------- tiny delay so recur clusters place before overlap GEMM ----
__global__ void k_delay() {
    long long s = clock64();
    while (clock64() - s < 100000LL) { __nanosleep(64); }
}

// ---------------- Work-stealing GEMM: C[4096,32000] = Apack @ Bhi^T (x2) + b_out ----
#define BM 128
#define BN 128
#define BK 64
#define KSTAGES 8    // 512/64
#define STG_SZ 32768 // 16KB A + 16KB B per stage
#define SMEM_GEMM (3 * STG_SZ)

__device__ __forceinline__ void cp16(uint32_t dst, const void* src) {
    asm volatile("cp.async.cg.shared.global [%0], [%1], 16;" :: "r"(dst), "l"(src));
}
__device__ __forceinline__ void ldsm4(uint32_t* r, uint32_t addr) {
    asm volatile("ldmatrix.sync.aligned.m8n8.x4.shared.b16 {%0,%1,%2,%3}, [%4];"
                 : "=r"(r[0]), "=r"(r[1]), "=r"(r[2]), "=r"(r[3]) : "r"(addr));
}
__device__ __forceinline__ void mma_f16(float* c, const uint32_t* a, uint32_t b0, uint32_t b1) {
    asm volatile(
        "mma.sync.aligned.m16n8k16.row.col.f32.f16.f16.f32 "
        "{%0,%1,%2,%3}, {%4,%5,%6,%7}, {%8,%9}, {%0,%1,%2,%3};"
        : "+f"(c[0]), "+f"(c[1]), "+f"(c[2]), "+f"(c[3])
        : "r"(a[0]), "r"(a[1]), "r"(a[2]), "r"(a[3]), "r"(b0), "r"(b1));
}

__global__ void __launch_bounds__(256, 2) k_gemm_ws(const float* __restrict__ b_out,
                                                    float* __restrict__ out,
                                                    int qfirst, int qstep, int qcount,
                                                    int do_spin) {
    extern __shared__ __half smem[];
    __shared__ int s_tile;
    __shared__ int s_to;
    const int tid  = threadIdx.x;
    const int warp = tid >> 5;
    const int lane = tid & 31;
    const int wm = warp >> 2;
    const int wn = warp & 3;
    const int lr = tid >> 3;
    const int lc = tid & 7;
    uint32_t s_base = (uint32_t)__cvta_generic_to_shared(smem);

    for (int qi = 0; qi < qcount; qi++) {
        const int q = qfirst + qi * qstep;
        if (do_spin) {
            if (tid == 0) {
                const int thr = (q + 1) * 64;
                int it = 0, to = 0;
                while (atomicAdd(&g_prog, 0) < thr) {
                    __nanosleep(512);
                    if (++it > 8000) { to = 1; break; }   // ~4ms safety: bail, cleanup kernel finishes
                }
                s_to = to;
            }
            __syncthreads();
            if (s_to) return;
            __threadfence();
        }

        while (true) {
            if (tid == 0) s_tile = atomicAdd(&g_ctr[q], 1);
            __syncthreads();
            const int tile = s_tile;
            __syncthreads();
            if (tile >= NTILE_Q) break;

            const int bM = (tile / 250) * 512 + q * BM;
            const int bN = (tile % 250) * BN;

            float acc[4][4][4];
#pragma unroll
            for (int i = 0; i < 4; i++)
#pragma unroll
                for (int j = 0; j < 4; j++)
#pragma unroll
                    for (int c = 0; c < 4; c++) acc[i][j][c] = 0.f;

            auto load_stage = [&](int s) {
                int buf = s % 3;
                uint32_t sA = s_base + buf * STG_SZ;
                uint32_t sB = sA + 16384;
                const __half* gA = g_Apack + (size_t)(bM + lr) * G2 + s * BK + lc * 8;
                const __half* gB = g_Bpack + (size_t)(bN + lr) * 256 + (s & 3) * BK + lc * 8;
#pragma unroll
                for (int i = 0; i < 4; i++) {
                    int row = lr + i * 32;
                    uint32_t dA = sA + row * 128 + ((lc ^ (row & 7)) << 4);
                    cp16(dA, gA + (size_t)i * 32 * G2);
                }
#pragma unroll
                for (int i = 0; i < 4; i++) {
                    int row = lr + i * 32;
                    uint32_t dB = sB + row * 128 + ((lc ^ (row & 7)) << 4);
                    cp16(dB, gB + (size_t)i * 32 * 256);
                }
                asm volatile("cp.async.commit_group;");
            };

            load_stage(0);
            load_stage(1);

            for (int s = 0; s < KSTAGES; s++) {
                if (s + 2 < KSTAGES) {
                    load_stage(s + 2);
                    asm volatile("cp.async.wait_group 2;");
                } else if (s + 1 < KSTAGES) {
                    asm volatile("cp.async.wait_group 1;");
                } else {
                    asm volatile("cp.async.wait_group 0;");
                }
                __syncthreads();

                int buf = s % 3;
                uint32_t baseA = s_base + buf * STG_SZ;
                uint32_t baseB = baseA + 16384;
                const int rin = lane & 15;
                const int hib = lane >> 4;

#pragma unroll
                for (int kk = 0; kk < 4; kk++) {
                    uint32_t afr[4][4];
#pragma unroll
                    for (int mt = 0; mt < 4; mt++) {
                        int row = wm * 64 + mt * 16 + rin;
                        int c16 = kk * 2 + hib;
                        uint32_t addr = baseA + row * 128 + ((c16 ^ (row & 7)) << 4);
                        ldsm4(afr[mt], addr);
                    }
                    uint32_t bfr[2][4];
#pragma unroll
                    for (int np = 0; np < 2; np++) {
                        int row = wn * 32 + np * 16 + rin;
                        int c16 = kk * 2 + hib;
                        uint32_t addr = baseB + row * 128 + ((c16 ^ (row & 7)) << 4);
                        ldsm4(bfr[np], addr);
                    }
#pragma unroll
                    for (int mt = 0; mt < 4; mt++)
#pragma unroll
                        for (int nt = 0; nt < 4; nt++) {
                            int np = nt >> 1, wv = nt & 1;
                            mma_f16(acc[mt][nt], afr[mt], bfr[np][wv], bfr[np][wv + 2]);
                        }
                }
                __syncthreads();
            }

            // epilogue
            const int tig = lane & 3;
            const int gid = lane >> 2;
#pragma unroll
            for (int nt = 0; nt < 4; nt++) {
                int col = bN + wn * 32 + nt * 8 + tig * 2;
                float2 bo = *reinterpret_cast<const float2*>(b_out + col);
#pragma unroll
                for (int mt = 0; mt < 4; mt++) {
                    int row0 = bM + wm * 64 + mt * 16 + gid;
#pragma unroll
                    for (int h = 0; h < 2; h++) {
                        int rr = row0 + h * 8;
                        int t = rr & 511, bb = rr >> 9;
                        if (t < TD) {
                            float2 v;
                            v.x = acc[mt][nt][2 * h + 0] + bo.x;
                            v.y = acc[mt][nt][2 * h + 1] + bo.y;
                            *reinterpret_cast<float2*>(out + ((size_t)(bb * TD + t)) * V_ + col) = v;
                        }
                    }
                }
            }
        }
    }
}

// ---------------- launch: overlap via capped work-stealing GEMM ----------------
extern "C" void kernel_launch(void* const* d_in, const int* in_sizes, int n_in,
                              void* d_out, int out_size) {
    (void)in_sizes; (void)n_in; (void)out_size;
    const int*   seqs  = (const int*)d_in[1];
    const float* emb   = (const float*)d_in[2];
    const float* W_ih  = (const float*)d_in[3];
    const float* W_hh  = (const float*)d_in[4];
    const float* b_ih  = (const float*)d_in[5];
    const float* b_hh  = (const float*)d_in[6];
    const float* W_out = (const float*)d_in[7];
    const float* b_out = (const float*)d_in[8];
    float* out = (float*)d_out;

    static cudaStream_t s2 = nullptr;
    static cudaEvent_t evg, evj;
    if (!s2) {
        cudaStreamCreateWithFlags(&s2, cudaStreamNonBlocking);
        cudaEventCreateWithFlags(&evg, cudaEventDisableTiming);
        cudaEventCreateWithFlags(&evj, cudaEventDisableTiming);
        cudaFuncSetAttribute(k_recur, cudaFuncAttributeMaxDynamicSharedMemorySize, RECUR_DSMEM);
        cudaFuncSetAttribute(k_gemm_ws, cudaFuncAttributeMaxDynamicSharedMemorySize, SMEM_GEMM);
    }

    // stream 0: prep -> bpack -> gx -> recur (single launch, resident on 64 SMs)
    k_prep_w<<<(2 * G3 * D_ + B_ * G2 + 255) / 256, 256>>>(W_ih, W_hh);
    k_bpack<<<V_, 256>>>(W_out);
    k_gx<<<256, 256>>>(seqs, emb, b_ih);
    cudaEventRecord(evg, 0);
    k_recur<<<64, 256, RECUR_DSMEM>>>(b_hh);

    // side stream joins capture via event wait (FIRST op on s2), then short delay
    // so recur's clusters place first, then capped work-stealing GEMM (quarters 0..2,
    // device-side spin on g_prog readiness).
    cudaStreamWaitEvent(s2, evg, 0);
    k_delay<<<1, 32, 0, s2>>>();
    k_gemm_ws<<<160, 256, SMEM_GEMM, s2>>>(b_out, out, 0, 1, 3, 1);
    cudaEventRecord(evj, s2);

    // stream 0: after recur, full-chip cleanup stealing quarters 3,2,1,0
    k_gemm_ws<<<296, 256, SMEM_GEMM>>>(b_out, out, 3, -1, 4, 0);
    cudaStreamWaitEvent(0, evj, 0);
}